// round 15
// baseline (speedup 1.0000x reference)
#include <cuda_runtime.h>
#include <cuda_fp16.h>
#include <cstdint>

#define NTOK 8192
#define KDIM 512
#define DDIM 4096

#define BM 128
#define BD 128
#define BK 64
#define KITERS (KDIM / BK)   // 8
#define DT (DDIM / BD)       // 32
#define NT (NTOK / BM)       // 64

#define OFF_A 0
#define OFF_B 16384
#define STAGE_BYTES 32768
#define STAGES 3
#define SMEM_TOTAL (STAGES * STAGE_BYTES)  // 98304 -> 2 CTAs/SM

__device__ __align__(16) __half g_Fh[NTOK * KDIM];   // fp16 F
__device__ __align__(16) __half g_Eh[DDIM * KDIM];   // fp16 E^T [d][k]
__device__ float g_partial[(size_t)DT * NTOK];
__device__ int g_cnt[NT];

__device__ __forceinline__ unsigned smem_u32(const void* p) {
    unsigned a;
    asm("{ .reg .u64 t; cvta.to.shared.u64 t, %1; cvt.u32.u64 %0, t; }" : "=r"(a) : "l"(p));
    return a;
}

#define CP16(s, g) \
    asm volatile("cp.async.cg.shared.global [%0], [%1], 16;" :: "r"(s), "l"(g) : "memory")
#define CP_COMMIT() asm volatile("cp.async.commit_group;" ::: "memory")
#define CP_WAIT1()  asm volatile("cp.async.wait_group 1;" ::: "memory")
#define CP_WAIT0()  asm volatile("cp.async.wait_group 0;" ::: "memory")

#define LDSM4(R, addr)                                                        \
    asm volatile("ldmatrix.sync.aligned.m8n8.x4.shared.b16 {%0,%1,%2,%3}, [%4];" \
        : "=r"((R)[0]), "=r"((R)[1]), "=r"((R)[2]), "=r"((R)[3]) : "r"(addr))

#define MMAH(C, A, b0, b1)                                                    \
    asm volatile("mma.sync.aligned.m16n8k16.row.col.f32.f16.f16.f32 "         \
        "{%0,%1,%2,%3}, {%4,%5,%6,%7}, {%8,%9}, {%0,%1,%2,%3};"               \
        : "+f"((C)[0]), "+f"((C)[1]), "+f"((C)[2]), "+f"((C)[3])              \
        : "r"((A)[0]), "r"((A)[1]), "r"((A)[2]), "r"((A)[3]), "r"(b0), "r"(b1))

// ---------------- prep: one kernel converts F + E^T and zeroes counters ----
// blocks [0, 2048): E^T transpose tiles (32x32); blocks [2048, ...): flat F.
#define E_BLOCKS (DDIM / 32 * KDIM / 32)           // 2048
#define F_BLOCKS ((NTOK * KDIM + 1023) / 1024)     // 4096 (1024 elems/block)
__global__ void conv_all_kernel(const float* __restrict__ f,
                                const float* __restrict__ e) {
    int bx = blockIdx.x;
    int tid = threadIdx.x;
    if (bx == 0 && tid < NT) g_cnt[tid] = 0;
    if (bx < E_BLOCKS) {
        __shared__ float t[32][33];
        int d0 = (bx & (DDIM / 32 - 1)) * 32;
        int k0 = (bx / (DDIM / 32)) * 32;
        int tx = tid & 31, ty = tid >> 5;
#pragma unroll
        for (int i = ty; i < 32; i += 8)
            t[i][tx] = e[(size_t)(k0 + i) * DDIM + d0 + tx];
        __syncthreads();
#pragma unroll
        for (int i = ty; i < 32; i += 8)
            g_Eh[(size_t)(d0 + i) * KDIM + k0 + tx] = __float2half(t[tx][i]);
    } else {
        int base = (bx - E_BLOCKS) * 1024 + tid;
#pragma unroll
        for (int r = 0; r < 4; r++) {
            int i = base + r * 256;
            if (i < NTOK * KDIM) g_Fh[i] = __float2half(f[i]);
        }
    }
}

// ---------------- main: fp16 GEMM + fused diagonal + fused final reduce ----
// Ring invariant: stage `it` lives in slot (it % 3); prefetch at iter `it`
// fills slot ((it+2) % 3), consumed at iter it-1 (top-of-loop barrier).
// Last iteration drains all cp.async groups.
// Final reduce: last CTA of each n-row sums the 32 partials in FIXED slot
// order (identical order to the old reduce kernel -> deterministic values).
__global__ void __launch_bounds__(256, 2)
mm_diag_kernel(const float* __restrict__ wmat, const float* __restrict__ bvec,
               float* __restrict__ out) {
    extern __shared__ char smem[];
    const unsigned sb = smem_u32(smem);
    const int tid  = threadIdx.x;
    const int lane = tid & 31;
    const int wid  = tid >> 5;
    const int wm   = wid & 1;   // 2 warps over tokens (64 each)
    const int wn   = wid >> 1;  // 4 warps over d (32 each)
    const int dg0  = blockIdx.x * BD;
    const int n0   = blockIdx.y * BM;
    const int g    = lane >> 2;
    const int cc   = lane & 3;

    const char* gA = (const char*)g_Fh;
    const char* gB = (const char*)g_Eh;

    // rows are 128B (64 halfs = one BK chunk); swizzle: chunk ^= (row & 7)
    auto load_stage = [&](int it, int s) {
        unsigned base = sb + (unsigned)s * STAGE_BYTES;
#pragma unroll
        for (int t = tid; t < 1024; t += 256) {  // A: 128 rows x 8 chunks(16B)
            int row = t >> 3, cs = t & 7;
            unsigned soff = (unsigned)(row * 128) + (unsigned)((cs ^ (row & 7)) << 4);
            size_t goff = ((size_t)(n0 + row) * KDIM + (size_t)it * BK + cs * 8) * 2;
            CP16(base + OFF_A + soff, gA + goff);
        }
#pragma unroll
        for (int t = tid; t < 1024; t += 256) {  // B: 128 d-rows x 8 chunks
            int row = t >> 3, cs = t & 7;
            unsigned soff = (unsigned)(row * 128) + (unsigned)((cs ^ (row & 7)) << 4);
            size_t goff = ((size_t)(dg0 + row) * KDIM + (size_t)it * BK + cs * 8) * 2;
            CP16(base + OFF_B + soff, gB + goff);
        }
    };

    load_stage(0, 0); CP_COMMIT();
    load_stage(1, 1); CP_COMMIT();

    // ldmatrix base offsets (kk=0); kk step -> XOR (kk<<5)
    unsigned offA[4], offB[2];
#pragma unroll
    for (int ma = 0; ma < 4; ma++) {
        int row = wm * 64 + ma * 16 + (lane & 15);
        int ch  = lane >> 4;
        offA[ma] = (unsigned)(row * 128) + (unsigned)((ch ^ (row & 7)) << 4);
    }
#pragma unroll
    for (int b = 0; b < 2; b++) {
        int row = wn * 32 + b * 16 + (lane & 15);
        int ch  = lane >> 4;
        offB[b] = (unsigned)(row * 128) + (unsigned)((ch ^ (row & 7)) << 4);
    }

    float c[4][4][4];
#pragma unroll
    for (int i = 0; i < 4; i++)
#pragma unroll
        for (int j = 0; j < 4; j++)
#pragma unroll
            for (int r = 0; r < 4; r++) c[i][j][r] = 0.f;

    for (int it = 0; it < KITERS; it++) {
        if (it == KITERS - 1) { CP_WAIT0(); } else { CP_WAIT1(); }
        __syncthreads();
        int slot = it % STAGES;
        unsigned baseA = sb + (unsigned)slot * STAGE_BYTES + OFF_A;
        unsigned baseB = sb + (unsigned)slot * STAGE_BYTES + OFF_B;

#pragma unroll
        for (int kk = 0; kk < 4; kk++) {
            unsigned kx = (unsigned)(kk << 5);
            uint32_t Ah[4][4], Bh[2][4];
#pragma unroll
            for (int ma = 0; ma < 4; ma++) LDSM4(Ah[ma], baseA + (offA[ma] ^ kx));
#pragma unroll
            for (int b = 0; b < 2; b++)    LDSM4(Bh[b],  baseB + (offB[b] ^ kx));
#pragma unroll
            for (int ma = 0; ma < 4; ma++)
#pragma unroll
                for (int b = 0; b < 2; b++) {
                    MMAH(c[ma][2 * b],     Ah[ma], Bh[b][0], Bh[b][2]);
                    MMAH(c[ma][2 * b + 1], Ah[ma], Bh[b][1], Bh[b][3]);
                }
        }

        if (it + 2 < KITERS) {
            load_stage(it + 2, (it + 2) % STAGES);
            CP_COMMIT();
        }
    }

    // ---- fused epilogue: rowacc[n] = sum_d (y + b[d]) * w[d][n] ----
    float rowacc[8];
#pragma unroll
    for (int ma = 0; ma < 4; ma++) {
#pragma unroll
        for (int rh = 0; rh < 2; rh++) {
            int n = n0 + wm * 64 + ma * 16 + g + rh * 8;
            float acc = 0.f;
#pragma unroll
            for (int nb = 0; nb < 4; nb++) {
#pragma unroll
                for (int cb = 0; cb < 2; cb++) {
                    int d = dg0 + wn * 32 + nb * 8 + cc * 2 + cb;
                    float y = c[ma][nb][rh * 2 + cb] + __ldg(&bvec[d]);
                    acc = fmaf(y, __ldg(&wmat[(size_t)d * NTOK + n]), acc);
                }
            }
            rowacc[ma * 2 + rh] = acc;
        }
    }
#pragma unroll
    for (int i = 0; i < 8; i++) {
        rowacc[i] += __shfl_xor_sync(0xFFFFFFFFu, rowacc[i], 1);
        rowacc[i] += __shfl_xor_sync(0xFFFFFFFFu, rowacc[i], 2);
    }

    // ---- intra-CTA reduction over wn (4 slices) via smem (pipeline done) ----
    __syncthreads();
    float* red = reinterpret_cast<float*>(smem);  // [4][128]
    if (cc == 0) {
#pragma unroll
        for (int ma = 0; ma < 4; ma++)
#pragma unroll
            for (int rh = 0; rh < 2; rh++) {
                int nloc = wm * 64 + ma * 16 + g + rh * 8;
                red[wn * 128 + nloc] = rowacc[ma * 2 + rh];
            }
    }
    __syncthreads();
    if (tid < 128) {
        float s = red[tid] + red[128 + tid] + red[256 + tid] + red[384 + tid];
        g_partial[(size_t)blockIdx.x * NTOK + n0 + tid] = s;
    }

    // ---- fused final reduce: last CTA of this n-row sums all 32 partials ----
    __threadfence();
    __shared__ int is_last;
    __syncthreads();           // partial store visible before arrival
    if (tid == 0) {
        int old = atomicAdd(&g_cnt[blockIdx.y], 1);
        is_last = (old == DT - 1);
    }
    __syncthreads();
    if (is_last) {
        __threadfence();       // acquire: see all other CTAs' partials
        if (tid < 128) {
            int n = n0 + tid;
            float s = 0.f;
#pragma unroll
            for (int x = 0; x < DT; x++)   // fixed order -> deterministic
                s += g_partial[(size_t)x * NTOK + n];
            out[n] = s;
        }
    }
}

// ---------------- launch ----------------
extern "C" void kernel_launch(void* const* d_in, const int* in_sizes, int n_in,
                              void* d_out, int out_size) {
    const float* features = (const float*)d_in[0];  // [8192, 512]
    const float* w        = (const float*)d_in[1];  // [4096, 8192]
    const float* E        = (const float*)d_in[2];  // [512, 4096]
    const float* b        = (const float*)d_in[3];  // [4096]
    float* out            = (float*)d_out;          // [8192]

    cudaFuncSetAttribute(mm_diag_kernel, cudaFuncAttributeMaxDynamicSharedMemorySize, SMEM_TOTAL);

    conv_all_kernel<<<E_BLOCKS + F_BLOCKS, 256>>>(features, E);
    mm_diag_kernel<<<dim3(DT, NT), 256, SMEM_TOTAL>>>(w, b, out);
}